// round 8
// baseline (speedup 1.0000x reference)
#include <cuda_runtime.h>
#include <cuda_fp16.h>
#include <math.h>
#include <math_constants.h>
#include <cstdint>

#define N_TOK 16384
#define DIMK  2048
#define NOUT  128
#define BM    64
#define NKB   128          // k16 blocks

#define BSCALE     512.0f
#define INV_BSCALE (1.0f / 512.0f)

// epilogue smem
#define L_STRIDE 132
#define SEL_OFF  (64 * L_STRIDE)
#define SMEM_BYTES ((64 * L_STRIDE + 128) * 4)

// output offsets (floats)
#define OUT_RW   0
#define OUT_SEL  32768
#define OUT_MASK 65536
#define OUT_LOAD 2162688

// ---- scratch (no allocations allowed) ----
// B fragments: [ib][n][t] -> uint4(hi0,hi1,lo0,lo1), +pad for prefetch
__device__ uint4 g_bfrag[128 * 128 * 4 + 2048];   // 1 MB + pad

__device__ __forceinline__ uint32_t pack_h2(float lo, float hi) {
    __half2 h = __halves2half2(__float2half_rn(lo), __float2half_rn(hi));
    return *reinterpret_cast<uint32_t*>(&h);
}
__device__ __forceinline__ void cvt2(float2 v, uint32_t& h, uint32_t& l) {
    const __half h0 = __float2half_rn(v.x), h1 = __float2half_rn(v.y);
    __half2 hp = __halves2half2(h0, h1);
    h = *reinterpret_cast<uint32_t*>(&hp);
    l = pack_h2(v.x - __half2float(h0), v.y - __half2float(h1));
}
__device__ __forceinline__ void mma_f16(float* c, const uint32_t* a,
                                        uint32_t b0, uint32_t b1) {
    asm volatile(
        "mma.sync.aligned.m16n8k16.row.col.f32.f16.f16.f32 "
        "{%0,%1,%2,%3}, {%4,%5,%6,%7}, {%8,%9}, {%0,%1,%2,%3};"
        : "+f"(c[0]), "+f"(c[1]), "+f"(c[2]), "+f"(c[3])
        : "r"(a[0]), "r"(a[1]), "r"(a[2]), "r"(a[3]), "r"(b0), "r"(b1));
}

// ============================================================================
// Pre-split B (w_gate;w_noise), scaled by BSCALE, into fp16 hi/lo fragments.
// ============================================================================
__global__ __launch_bounds__(256) void presplit_kernel(
    const float* __restrict__ wg, const float* __restrict__ wn)
{
    const int idx = blockIdx.x * 256 + threadIdx.x;   // 0..65535
    const int t  = idx & 3;
    const int n  = (idx >> 2) & 127;
    const int ib = idx >> 9;
    const float* src = (n < 64) ? (wg + (size_t)n * DIMK)
                                : (wn + (size_t)(n - 64) * DIMK);
    const int k0 = ib * 16 + 2 * t;
    const float v0 = src[k0]     * BSCALE;
    const float v1 = src[k0 + 1] * BSCALE;
    const float v2 = src[k0 + 8] * BSCALE;
    const float v3 = src[k0 + 9] * BSCALE;
    const __half h0 = __float2half_rn(v0), h1 = __float2half_rn(v1);
    const __half h2 = __float2half_rn(v2), h3 = __float2half_rn(v3);
    uint4 o;
    {
        __half2 p;
        p = __halves2half2(h0, h1); o.x = *reinterpret_cast<uint32_t*>(&p);
        p = __halves2half2(h2, h3); o.y = *reinterpret_cast<uint32_t*>(&p);
    }
    o.z = pack_h2(v0 - __half2float(h0), v1 - __half2float(h1));
    o.w = pack_h2(v2 - __half2float(h2), v3 - __half2float(h3));
    g_bfrag[idx] = o;
}

// ============================================================================
// Fused fp16x3 GEMM + routing + mask. No smem / barriers in the mainloop:
// A fragments LDG'd per-warp (L1 reuse x4) and split in registers.
// CTA: 64 tokens x 128 cols, 8 warps (2m x 4n), warp tile 32x32, m16n8k16.
// ============================================================================
__global__ __launch_bounds__(256, 2) void gemm_kernel(
    const float* __restrict__ x,
    const float* __restrict__ noise,
    float* __restrict__ out)
{
    extern __shared__ uint32_t sm[];
    const int tid  = threadIdx.x;
    const int wid  = tid >> 5;
    const int lane = tid & 31;
    const int g    = lane >> 2;
    const int t    = lane & 3;
    const int warp_m = wid & 1;
    const int warp_n = wid >> 1;
    const int blockRow = blockIdx.x * BM;
    const int arow0 = warp_m * 32;
    const int ncol0 = warp_n * 32;

    // A fragment row pointers (per mf: rows r and r+8), k offset 2t
    const float* a00 = x + (size_t)(blockRow + arow0 + g)      * DIMK + 2 * t;
    const float* a01 = a00 + 8 * DIMK;
    const float* a10 = a00 + 16 * DIMK;
    const float* a11 = a00 + 24 * DIMK;

    const uint4* bbase = g_bfrag + ((ncol0 + g) * 4 + t);

    float acc[2][4][4];
    #pragma unroll
    for (int mf = 0; mf < 2; mf++)
        #pragma unroll
        for (int nf = 0; nf < 4; nf++)
            #pragma unroll
            for (int r = 0; r < 4; r++) acc[mf][nf][r] = 0.f;

    // double buffers: raw A float2 frags + B uint4 frags
    float2 Araw[2][2][4];   // [buf][mf][pos]
    uint4  Bbuf[2][4];

    // ---- prologue: load kb=0 ----
    #pragma unroll
    for (int nf = 0; nf < 4; nf++) Bbuf[0][nf] = bbase[nf * 32];
    Araw[0][0][0] = *(const float2*)(a00);
    Araw[0][0][1] = *(const float2*)(a01);
    Araw[0][0][2] = *(const float2*)(a00 + 8);
    Araw[0][0][3] = *(const float2*)(a01 + 8);
    Araw[0][1][0] = *(const float2*)(a10);
    Araw[0][1][1] = *(const float2*)(a11);
    Araw[0][1][2] = *(const float2*)(a10 + 8);
    Araw[0][1][3] = *(const float2*)(a11 + 8);

    #pragma unroll 2
    for (int kb = 0; kb < NKB; kb++) {
        const int cur = kb & 1, nxt = cur ^ 1;
        // prefetch kb+1 (clamped; B pad covers OOB)
        const int kn = (kb + 1 < NKB) ? (kb + 1) : 0;
        {
            const int ko = kn * 16;
            Araw[nxt][0][0] = *(const float2*)(a00 + ko);
            Araw[nxt][0][1] = *(const float2*)(a01 + ko);
            Araw[nxt][0][2] = *(const float2*)(a00 + ko + 8);
            Araw[nxt][0][3] = *(const float2*)(a01 + ko + 8);
            Araw[nxt][1][0] = *(const float2*)(a10 + ko);
            Araw[nxt][1][1] = *(const float2*)(a11 + ko);
            Araw[nxt][1][2] = *(const float2*)(a10 + ko + 8);
            Araw[nxt][1][3] = *(const float2*)(a11 + ko + 8);
            const uint4* bn = bbase + (size_t)(kb + 1) * 512;
            #pragma unroll
            for (int nf = 0; nf < 4; nf++) Bbuf[nxt][nf] = bn[nf * 32];
        }

        #pragma unroll
        for (int mf = 0; mf < 2; mf++) {
            uint32_t ah[4], al[4];
            cvt2(Araw[cur][mf][0], ah[0], al[0]);
            cvt2(Araw[cur][mf][1], ah[1], al[1]);
            cvt2(Araw[cur][mf][2], ah[2], al[2]);
            cvt2(Araw[cur][mf][3], ah[3], al[3]);
            #pragma unroll
            for (int nf = 0; nf < 4; nf++) {
                const uint32_t bh0 = Bbuf[cur][nf].x, bh1 = Bbuf[cur][nf].y;
                const uint32_t bl0 = Bbuf[cur][nf].z, bl1 = Bbuf[cur][nf].w;
                mma_f16(acc[mf][nf], ah, bh0, bh1);
                mma_f16(acc[mf][nf], ah, bl0, bl1);
                mma_f16(acc[mf][nf], al, bh0, bh1);
            }
        }
    }

    // ======================= fused epilogue =======================
    float* Ls = (float*)sm;
    int*   sel_s = (int*)(sm + SEL_OFF);
    #pragma unroll
    for (int mf = 0; mf < 2; mf++) {
        const int m = arow0 + mf * 16 + g;
        #pragma unroll
        for (int nf = 0; nf < 4; nf++) {
            const int n = ncol0 + nf * 8 + 2 * t;
            *(float2*)(Ls + m * L_STRIDE + n) =
                make_float2(acc[mf][nf][0] * INV_BSCALE, acc[mf][nf][1] * INV_BSCALE);
            *(float2*)(Ls + (m + 8) * L_STRIDE + n) =
                make_float2(acc[mf][nf][2] * INV_BSCALE, acc[mf][nf][3] * INV_BSCALE);
        }
    }
    __syncthreads();

    for (int tk = 0; tk < 8; tk++) {
        const int nl = wid * 8 + tk;
        const int n  = blockRow + nl;

        const float2 rv = *(const float2*)(Ls + nl * L_STRIDE + 2 * lane);
        const float2 wv = *(const float2*)(Ls + nl * L_STRIDE + 64 + 2 * lane);
        const float2 nz = *(const float2*)(noise + (size_t)n * 64 + 2 * lane);

        float rl[2], sv[2], sd[2];
        rl[0] = rv.x; rl[1] = rv.y;
        {
            const float sp0 = fmaxf(wv.x, 0.f) + log1pf(expf(-fabsf(wv.x)));
            const float sp1 = fmaxf(wv.y, 0.f) + log1pf(expf(-fabsf(wv.y)));
            sd[0] = sp0 + 0.01f;
            sd[1] = sp1 + 0.01f;
            sv[0] = fmaf(nz.x, sd[0], rl[0]);
            sv[1] = fmaf(nz.y, sd[1], rl[1]);
        }

        float vtop[3]; int itop[3];
        float cur0 = sv[0], cur1 = sv[1];
        #pragma unroll
        for (int r = 0; r < 3; r++) {
            float bv; int bi;
            if (cur0 >= cur1) { bv = cur0; bi = lane * 2; }
            else              { bv = cur1; bi = lane * 2 + 1; }
            #pragma unroll
            for (int off = 16; off; off >>= 1) {
                const float ov = __shfl_xor_sync(0xffffffffu, bv, off);
                const int   oi = __shfl_xor_sync(0xffffffffu, bi, off);
                if (ov > bv || (ov == bv && oi < bi)) { bv = ov; bi = oi; }
            }
            vtop[r] = bv; itop[r] = bi;
            if ((bi >> 1) == lane) {
                if (bi & 1) cur1 = -CUDART_INF_F; else cur0 = -CUDART_INF_F;
            }
        }

        const float thr2 = vtop[1];
        const float thr3 = vtop[2];

        if (lane == 0) {
            const float a = expf(vtop[1] - vtop[0]);
            const float s = 1.f + a;
            out[OUT_RW  + n * 2 + 0] = 1.f / s;
            out[OUT_RW  + n * 2 + 1] = a / s;
            out[OUT_SEL + n * 2 + 0] = (float)itop[0];
            out[OUT_SEL + n * 2 + 1] = (float)itop[1];
            sel_s[nl * 2 + 0] = itop[0];
            sel_s[nl * 2 + 1] = itop[1];
        }

        float2 ld;
        {
            const bool in0 = sv[0] > thr3;
            const bool in1 = sv[1] > thr3;
            ld.x = normcdff((rl[0] - (in0 ? thr3 : thr2)) / sd[0]);
            ld.y = normcdff((rl[1] - (in1 ? thr3 : thr2)) / sd[1]);
        }
        *(float2*)(out + OUT_LOAD + (size_t)n * 64 + 2 * lane) = ld;
    }
    __syncthreads();

    {
        const int row = tid >> 1;
        const int e   = row >> 1;
        const int j   = row & 1;
        float* mrow = out + OUT_MASK + (size_t)row * N_TOK + blockRow + (tid & 1) * 32;
        const int nl0 = (tid & 1) * 32;
        #pragma unroll
        for (int q = 0; q < 8; q++) {
            const int nb = nl0 + q * 4;
            float4 v;
            v.x = (sel_s[(nb + 0) * 2 + j] == e) ? 1.f : 0.f;
            v.y = (sel_s[(nb + 1) * 2 + j] == e) ? 1.f : 0.f;
            v.z = (sel_s[(nb + 2) * 2 + j] == e) ? 1.f : 0.f;
            v.w = (sel_s[(nb + 3) * 2 + j] == e) ? 1.f : 0.f;
            *(float4*)(mrow + q * 4) = v;
        }
    }
}

extern "C" void kernel_launch(void* const* d_in, const int* in_sizes, int n_in,
                              void* d_out, int out_size)
{
    const float* x     = (const float*)d_in[0];
    const float* wg    = (const float*)d_in[1];
    const float* wn    = (const float*)d_in[2];
    const float* noise = (const float*)d_in[3];
    float* out = (float*)d_out;

    cudaFuncSetAttribute(gemm_kernel,
                         cudaFuncAttributeMaxDynamicSharedMemorySize, SMEM_BYTES);

    presplit_kernel<<<256, 256>>>(wg, wn);
    gemm_kernel<<<N_TOK / BM, 256, SMEM_BYTES>>>(x, noise, out);
}

// round 9
// speedup vs baseline: 1.2083x; 1.2083x over previous
#include <cuda_runtime.h>
#include <cuda_fp16.h>
#include <math.h>
#include <math_constants.h>
#include <cstdint>

#define N_TOK 16384
#define DIMK  2048
#define NOUT  128
#define BM    64
#define BK    64           // fp32 k elems per smem stage (4 x k16 blocks)
#define NCHUNK (DIMK / BK)      // 32
// A smem: packed f16x2 (hi,lo), u32 row stride 36 (conflict-free LDSM + STS.128)
#define PAD_U 36
#define A_SZU (BM * PAD_U)                  // 2304 u32
#define STAGE_U (2 * A_SZU)                 // AH + AL
#define SMEM_BYTES (2 * STAGE_U * 4)        // 36864 B  (also covers epilogue use)

#define BSCALE     512.0f
#define INV_BSCALE (1.0f / 512.0f)

// epilogue smem layout (reusing mainloop buffers)
#define L_STRIDE 132
#define SEL_OFF  (64 * L_STRIDE)

// output offsets (floats)
#define OUT_RW   0
#define OUT_SEL  32768
#define OUT_MASK 65536
#define OUT_LOAD 2162688

// ---- scratch (no allocations allowed) ----
__device__ uint4 g_bfrag[128 * 128 * 4 + 2048];   // 1 MB + prefetch pad

__device__ __forceinline__ uint32_t smem_u32(const void* p) {
    uint32_t a;
    asm("{ .reg .u64 t; cvta.to.shared.u64 t, %1; cvt.u32.u64 %0, t; }"
        : "=r"(a) : "l"(p));
    return a;
}
__device__ __forceinline__ uint32_t pack_h2(float lo, float hi) {
    __half2 h = __halves2half2(__float2half_rn(lo), __float2half_rn(hi));
    return *reinterpret_cast<uint32_t*>(&h);
}
__device__ __forceinline__ void mma_f16(float* c, const uint32_t* a,
                                        uint32_t b0, uint32_t b1) {
    asm volatile(
        "mma.sync.aligned.m16n8k16.row.col.f32.f16.f16.f32 "
        "{%0,%1,%2,%3}, {%4,%5,%6,%7}, {%8,%9}, {%0,%1,%2,%3};"
        : "+f"(c[0]), "+f"(c[1]), "+f"(c[2]), "+f"(c[3])
        : "r"(a[0]), "r"(a[1]), "r"(a[2]), "r"(a[3]), "r"(b0), "r"(b1));
}
__device__ __forceinline__ void ldsm_x4(uint32_t* r, uint32_t addr) {
    asm volatile("ldmatrix.sync.aligned.m8n8.x4.shared.b16 {%0,%1,%2,%3}, [%4];"
        : "=r"(r[0]), "=r"(r[1]), "=r"(r[2]), "=r"(r[3]) : "r"(addr));
}

// ============================================================================
// Pre-split B (w_gate;w_noise), scaled by BSCALE, into fp16 hi/lo fragments.
// ============================================================================
__global__ __launch_bounds__(256) void presplit_kernel(
    const float* __restrict__ wg, const float* __restrict__ wn)
{
    const int idx = blockIdx.x * 256 + threadIdx.x;   // 0..65535
    const int t  = idx & 3;
    const int n  = (idx >> 2) & 127;
    const int ib = idx >> 9;
    const float* src = (n < 64) ? (wg + (size_t)n * DIMK)
                                : (wn + (size_t)(n - 64) * DIMK);
    const int k0 = ib * 16 + 2 * t;
    const float v0 = src[k0]     * BSCALE;
    const float v1 = src[k0 + 1] * BSCALE;
    const float v2 = src[k0 + 8] * BSCALE;
    const float v3 = src[k0 + 9] * BSCALE;
    const __half h0 = __float2half_rn(v0), h1 = __float2half_rn(v1);
    const __half h2 = __float2half_rn(v2), h3 = __float2half_rn(v3);
    uint4 o;
    {
        __half2 p;
        p = __halves2half2(h0, h1); o.x = *reinterpret_cast<uint32_t*>(&p);
        p = __halves2half2(h2, h3); o.y = *reinterpret_cast<uint32_t*>(&p);
    }
    o.z = pack_h2(v0 - __half2float(h0), v1 - __half2float(h1));
    o.w = pack_h2(v2 - __half2float(h2), v3 - __half2float(h3));
    g_bfrag[idx] = o;
}

// ============================================================================
// Fused fp16x3 GEMM + routing + mask.
// CTA: 64 tokens x 128 cols, 8 warps (2m x 4n), warp tile 32x32, m16n8k16.
// A frags via ldmatrix.x4 (double-buffered). MMA stream is pass-major so
// accumulator reuse distance is 8 MMAs (breaks the RAW chain).
// ============================================================================
__global__ __launch_bounds__(256, 2) void gemm_kernel(
    const float* __restrict__ x,
    const float* __restrict__ noise,
    float* __restrict__ out)
{
    extern __shared__ uint32_t sm[];
    const int tid  = threadIdx.x;
    const int wid  = tid >> 5;
    const int lane = tid & 31;
    const int g    = lane >> 2;
    const int t    = lane & 3;
    const int warp_m = wid & 1;
    const int warp_n = wid >> 1;
    const int blockRow = blockIdx.x * BM;
    const int arow0 = warp_m * 32;
    const int ncol0 = warp_n * 32;

    const int ar  = tid >> 2;
    const int akq = (tid & 3) * 16;
    const float* asrc = x + (size_t)(blockRow + ar) * DIMK + akq;
    const int acol = (tid & 3) * 8;

    const uint4* bbase = g_bfrag + ((ncol0 + g) * 4 + t);

    // ldmatrix pointer for A fragments: lane -> (row, 16B column)
    const int arow_l = arow0 + ((lane >> 3) & 1) * 8 + (lane & 7);
    const uint32_t smem_b = smem_u32(sm);
    const uint32_t afrag = smem_b + (uint32_t)(arow_l * PAD_U + (lane >> 4) * 4) * 4;

    float acc[2][4][4];
    #pragma unroll
    for (int mf = 0; mf < 2; mf++)
        #pragma unroll
        for (int nf = 0; nf < 4; nf++)
            #pragma unroll
            for (int r = 0; r < 4; r++) acc[mf][nf][r] = 0.f;

    float4 aL[4];

    // ---- prologue: A chunk 0 -> smem stage 0 ----
    #pragma unroll
    for (int q = 0; q < 4; q++) aL[q] = *(const float4*)(asrc + q * 4);
    {
        uint32_t* AH = sm;
        uint32_t* AL = sm + A_SZU;
        #pragma unroll
        for (int q = 0; q < 2; q++) {
            const float f0 = aL[2*q].x,   f1 = aL[2*q].y,
                        f2 = aL[2*q].z,   f3 = aL[2*q].w,
                        f4 = aL[2*q+1].x, f5 = aL[2*q+1].y,
                        f6 = aL[2*q+1].z, f7 = aL[2*q+1].w;
            const __half h0=__float2half_rn(f0), h1=__float2half_rn(f1),
                         h2=__float2half_rn(f2), h3=__float2half_rn(f3),
                         h4=__float2half_rn(f4), h5=__float2half_rn(f5),
                         h6=__float2half_rn(f6), h7=__float2half_rn(f7);
            uint4 hv, lv;
            { __half2 p=__halves2half2(h0,h1); hv.x=*reinterpret_cast<uint32_t*>(&p);
              p=__halves2half2(h2,h3); hv.y=*reinterpret_cast<uint32_t*>(&p);
              p=__halves2half2(h4,h5); hv.z=*reinterpret_cast<uint32_t*>(&p);
              p=__halves2half2(h6,h7); hv.w=*reinterpret_cast<uint32_t*>(&p); }
            lv.x = pack_h2(f0-__half2float(h0), f1-__half2float(h1));
            lv.y = pack_h2(f2-__half2float(h2), f3-__half2float(h3));
            lv.z = pack_h2(f4-__half2float(h4), f5-__half2float(h5));
            lv.w = pack_h2(f6-__half2float(h6), f7-__half2float(h7));
            *(uint4*)(AH + ar * PAD_U + acol + q * 4) = hv;
            *(uint4*)(AL + ar * PAD_U + acol + q * 4) = lv;
        }
    }
    __syncthreads();

    uint32_t Afh[2][2][4], Afl[2][2][4];   // [buf][mf][4]
    uint4 Bbuf[2][4];
    #pragma unroll
    for (int nf = 0; nf < 4; nf++) Bbuf[0][nf] = bbase[nf * 32];
    ldsm_x4(Afh[0][0], afrag);
    ldsm_x4(Afh[0][1], afrag + 2304);
    ldsm_x4(Afl[0][0], afrag + A_SZU * 4);
    ldsm_x4(Afl[0][1], afrag + A_SZU * 4 + 2304);

    for (int i = 0; i < NCHUNK; i++) {
        if (i + 1 < NCHUNK) {
            #pragma unroll
            for (int q = 0; q < 4; q++)
                aL[q] = *(const float4*)(asrc + (i + 1) * BK + q * 4);
        }

        const uint32_t stb = afrag + (uint32_t)(i & 1) * (STAGE_U * 4);
        const uint4* bi = bbase + (size_t)i * 2048;

        #pragma unroll
        for (int ks = 0; ks < 4; ks++) {
            const int cur = ks & 1, nxt = cur ^ 1;
            if (ks < 3) {
                ldsm_x4(Afh[nxt][0], stb + (ks + 1) * 32);
                ldsm_x4(Afh[nxt][1], stb + 2304 + (ks + 1) * 32);
                ldsm_x4(Afl[nxt][0], stb + A_SZU * 4 + (ks + 1) * 32);
                ldsm_x4(Afl[nxt][1], stb + A_SZU * 4 + 2304 + (ks + 1) * 32);
            }
            const uint4* bn = (ks < 3) ? (bi + (ks + 1) * 512) : (bi + 2048);
            #pragma unroll
            for (int nf = 0; nf < 4; nf++) Bbuf[nxt][nf] = bn[nf * 32];

            // pass-major MMA order: 8 independent accs per pass
            #pragma unroll
            for (int nf = 0; nf < 4; nf++) {        // hi * hi
                mma_f16(acc[0][nf], Afh[cur][0], Bbuf[cur][nf].x, Bbuf[cur][nf].y);
                mma_f16(acc[1][nf], Afh[cur][1], Bbuf[cur][nf].x, Bbuf[cur][nf].y);
            }
            #pragma unroll
            for (int nf = 0; nf < 4; nf++) {        // hi * lo
                mma_f16(acc[0][nf], Afh[cur][0], Bbuf[cur][nf].z, Bbuf[cur][nf].w);
                mma_f16(acc[1][nf], Afh[cur][1], Bbuf[cur][nf].z, Bbuf[cur][nf].w);
            }
            #pragma unroll
            for (int nf = 0; nf < 4; nf++) {        // lo * hi
                mma_f16(acc[0][nf], Afl[cur][0], Bbuf[cur][nf].x, Bbuf[cur][nf].y);
                mma_f16(acc[1][nf], Afl[cur][1], Bbuf[cur][nf].x, Bbuf[cur][nf].y);
            }
        }

        if (i + 1 < NCHUNK) {
            uint32_t* AHn = sm + ((i + 1) & 1) * STAGE_U;
            uint32_t* ALn = AHn + A_SZU;
            #pragma unroll
            for (int q = 0; q < 2; q++) {
                const float f0 = aL[2*q].x,   f1 = aL[2*q].y,
                            f2 = aL[2*q].z,   f3 = aL[2*q].w,
                            f4 = aL[2*q+1].x, f5 = aL[2*q+1].y,
                            f6 = aL[2*q+1].z, f7 = aL[2*q+1].w;
                const __half h0=__float2half_rn(f0), h1=__float2half_rn(f1),
                             h2=__float2half_rn(f2), h3=__float2half_rn(f3),
                             h4=__float2half_rn(f4), h5=__float2half_rn(f5),
                             h6=__float2half_rn(f6), h7=__float2half_rn(f7);
                uint4 hv, lv;
                { __half2 p=__halves2half2(h0,h1); hv.x=*reinterpret_cast<uint32_t*>(&p);
                  p=__halves2half2(h2,h3); hv.y=*reinterpret_cast<uint32_t*>(&p);
                  p=__halves2half2(h4,h5); hv.z=*reinterpret_cast<uint32_t*>(&p);
                  p=__halves2half2(h6,h7); hv.w=*reinterpret_cast<uint32_t*>(&p); }
                lv.x = pack_h2(f0-__half2float(h0), f1-__half2float(h1));
                lv.y = pack_h2(f2-__half2float(h2), f3-__half2float(h3));
                lv.z = pack_h2(f4-__half2float(h4), f5-__half2float(h5));
                lv.w = pack_h2(f6-__half2float(h6), f7-__half2float(h7));
                *(uint4*)(AHn + ar * PAD_U + acol + q * 4) = hv;
                *(uint4*)(ALn + ar * PAD_U + acol + q * 4) = lv;
            }
        }
        __syncthreads();

        if (i + 1 < NCHUNK) {
            const uint32_t nstb = afrag + (uint32_t)((i + 1) & 1) * (STAGE_U * 4);
            ldsm_x4(Afh[0][0], nstb);
            ldsm_x4(Afh[0][1], nstb + 2304);
            ldsm_x4(Afl[0][0], nstb + A_SZU * 4);
            ldsm_x4(Afl[0][1], nstb + A_SZU * 4 + 2304);
        }
    }

    // ======================= fused epilogue =======================
    float* Ls = (float*)sm;
    int*   sel_s = (int*)(sm + SEL_OFF);
    #pragma unroll
    for (int mf = 0; mf < 2; mf++) {
        const int m = arow0 + mf * 16 + g;
        #pragma unroll
        for (int nf = 0; nf < 4; nf++) {
            const int n = ncol0 + nf * 8 + 2 * t;
            *(float2*)(Ls + m * L_STRIDE + n) =
                make_float2(acc[mf][nf][0] * INV_BSCALE, acc[mf][nf][1] * INV_BSCALE);
            *(float2*)(Ls + (m + 8) * L_STRIDE + n) =
                make_float2(acc[mf][nf][2] * INV_BSCALE, acc[mf][nf][3] * INV_BSCALE);
        }
    }
    __syncthreads();

    for (int tk = 0; tk < 8; tk++) {
        const int nl = wid * 8 + tk;
        const int n  = blockRow + nl;

        const float2 rv = *(const float2*)(Ls + nl * L_STRIDE + 2 * lane);
        const float2 wv = *(const float2*)(Ls + nl * L_STRIDE + 64 + 2 * lane);
        const float2 nz = *(const float2*)(noise + (size_t)n * 64 + 2 * lane);

        float rl[2], sv[2], sd[2];
        rl[0] = rv.x; rl[1] = rv.y;
        {
            const float sp0 = fmaxf(wv.x, 0.f) + log1pf(expf(-fabsf(wv.x)));
            const float sp1 = fmaxf(wv.y, 0.f) + log1pf(expf(-fabsf(wv.y)));
            sd[0] = sp0 + 0.01f;
            sd[1] = sp1 + 0.01f;
            sv[0] = fmaf(nz.x, sd[0], rl[0]);
            sv[1] = fmaf(nz.y, sd[1], rl[1]);
        }

        float vtop[3]; int itop[3];
        float cur0 = sv[0], cur1 = sv[1];
        #pragma unroll
        for (int r = 0; r < 3; r++) {
            float bv; int bi;
            if (cur0 >= cur1) { bv = cur0; bi = lane * 2; }
            else              { bv = cur1; bi = lane * 2 + 1; }
            #pragma unroll
            for (int off = 16; off; off >>= 1) {
                const float ov = __shfl_xor_sync(0xffffffffu, bv, off);
                const int   oi = __shfl_xor_sync(0xffffffffu, bi, off);
                if (ov > bv || (ov == bv && oi < bi)) { bv = ov; bi = oi; }
            }
            vtop[r] = bv; itop[r] = bi;
            if ((bi >> 1) == lane) {
                if (bi & 1) cur1 = -CUDART_INF_F; else cur0 = -CUDART_INF_F;
            }
        }

        const float thr2 = vtop[1];
        const float thr3 = vtop[2];

        if (lane == 0) {
            const float a = expf(vtop[1] - vtop[0]);
            const float s = 1.f + a;
            out[OUT_RW  + n * 2 + 0] = 1.f / s;
            out[OUT_RW  + n * 2 + 1] = a / s;
            out[OUT_SEL + n * 2 + 0] = (float)itop[0];
            out[OUT_SEL + n * 2 + 1] = (float)itop[1];
            sel_s[nl * 2 + 0] = itop[0];
            sel_s[nl * 2 + 1] = itop[1];
        }

        float2 ld;
        {
            const bool in0 = sv[0] > thr3;
            const bool in1 = sv[1] > thr3;
            ld.x = normcdff((rl[0] - (in0 ? thr3 : thr2)) / sd[0]);
            ld.y = normcdff((rl[1] - (in1 ? thr3 : thr2)) / sd[1]);
        }
        *(float2*)(out + OUT_LOAD + (size_t)n * 64 + 2 * lane) = ld;
    }
    __syncthreads();

    {
        const int row = tid >> 1;
        const int e   = row >> 1;
        const int j   = row & 1;
        float* mrow = out + OUT_MASK + (size_t)row * N_TOK + blockRow + (tid & 1) * 32;
        const int nl0 = (tid & 1) * 32;
        #pragma unroll
        for (int q = 0; q < 8; q++) {
            const int nb = nl0 + q * 4;
            float4 v;
            v.x = (sel_s[(nb + 0) * 2 + j] == e) ? 1.f : 0.f;
            v.y = (sel_s[(nb + 1) * 2 + j] == e) ? 1.f : 0.f;
            v.z = (sel_s[(nb + 2) * 2 + j] == e) ? 1.f : 0.f;
            v.w = (sel_s[(nb + 3) * 2 + j] == e) ? 1.f : 0.f;
            *(float4*)(mrow + q * 4) = v;
        }
    }
}

extern "C" void kernel_launch(void* const* d_in, const int* in_sizes, int n_in,
                              void* d_out, int out_size)
{
    const float* x     = (const float*)d_in[0];
    const float* wg    = (const float*)d_in[1];
    const float* wn    = (const float*)d_in[2];
    const float* noise = (const float*)d_in[3];
    float* out = (float*)d_out;

    cudaFuncSetAttribute(gemm_kernel,
                         cudaFuncAttributeMaxDynamicSharedMemorySize, SMEM_BYTES);

    presplit_kernel<<<256, 256>>>(wg, wn);
    gemm_kernel<<<N_TOK / BM, 256, SMEM_BYTES>>>(x, noise, out);
}